// round 16
// baseline (speedup 1.0000x reference)
#include <cuda_runtime.h>
#include <cuda_fp16.h>
#include <cstdint>

#define EPS    1e-5f
#define ALPHA  0.2f
#define MAX_O  50000
#define MAX_T  200000

// ---------------- scratch (static device globals; no allocation) -------------
__device__ float  g_A1[(size_t)MAX_T * 512];
__device__ __half g_A2[(size_t)MAX_T * 1152];
__device__ float  g_A4[(size_t)MAX_O * 128];
__device__ int    g_deg[MAX_O];
__device__ int    g_off[MAX_O + 1];
__device__ int    g_cur[MAX_O];
__device__ int    g_elist[2 * MAX_T];
__device__ int    g_es[MAX_T];
__device__ int    g_eo[MAX_T];
__device__ int    g_flag32;
__device__ __half g_objh[(size_t)MAX_O * 128];
__device__ __half g_predh[(size_t)MAX_T * 128];
__device__ __half g_xh[(size_t)MAX_T * 512];
#define WT_TOTAL 1114112
__device__ __half g_wt[WT_TOTAL];
__device__ float g_sum[2304];
__device__ float g_sq[2304];
__device__ float g_cA[2304];
__device__ float g_cB[2304];

// ======================= PTX wrappers =========================================
__device__ __forceinline__ uint32_t smem_to_u32(const void* p) {
    uint32_t a;
    asm("{ .reg .u64 t; cvta.to.shared.u64 t, %1; cvt.u32.u64 %0, t; }" : "=r"(a) : "l"(p));
    return a;
}
__device__ __forceinline__ void ldsm_x4(uint32_t addr, uint32_t* r) {
    asm volatile("ldmatrix.sync.aligned.m8n8.x4.shared.b16 {%0,%1,%2,%3}, [%4];"
        : "=r"(r[0]), "=r"(r[1]), "=r"(r[2]), "=r"(r[3]) : "r"(addr));
}
__device__ __forceinline__ void mma_f16(float* c, const uint32_t* a, const uint32_t* b) {
    asm volatile("mma.sync.aligned.m16n8k16.row.col.f32.f16.f16.f32 "
        "{%0,%1,%2,%3},{%4,%5,%6,%7},{%8,%9},{%0,%1,%2,%3};"
        : "+f"(c[0]), "+f"(c[1]), "+f"(c[2]), "+f"(c[3])
        : "r"(a[0]), "r"(a[1]), "r"(a[2]), "r"(a[3]), "r"(b[0]), "r"(b[1]));
}
__device__ __forceinline__ void cp16(uint32_t dst, const void* src) {
    asm volatile("cp.async.cg.shared.global [%0], [%1], 16;" :: "r"(dst), "l"(src));
}
#define CP_COMMIT() asm volatile("cp.async.commit_group;" ::: "memory")
#define CP_WAIT(n)  asm volatile("cp.async.wait_group %0;" :: "n"(n) : "memory")

__device__ __forceinline__ void store2(float* C, long off, float v0, float v1) {
    *reinterpret_cast<float2*>(C + off) = make_float2(v0, v1);
}
__device__ __forceinline__ void store2(__half* C, long off, float v0, float v1) {
    *reinterpret_cast<__half2*>(C + off) = __floats2half2_rn(v0, v1);
}

__device__ __forceinline__ float4 bn4(float4 v, float4 a, float4 b) {
    v.x = fmaf(v.x, a.x, b.x); v.x = v.x >= 0.f ? v.x : ALPHA * v.x;
    v.y = fmaf(v.y, a.y, b.y); v.y = v.y >= 0.f ? v.y : ALPHA * v.y;
    v.z = fmaf(v.z, a.z, b.z); v.z = v.z >= 0.f ? v.z : ALPHA * v.z;
    v.w = fmaf(v.w, a.w, b.w); v.w = v.w >= 0.f ? v.w : ALPHA * v.w;
    return v;
}
__device__ __forceinline__ float4 ld_h4(const __half* p) {
    uint2 raw = *reinterpret_cast<const uint2*>(p);
    __half2 p0 = *reinterpret_cast<__half2*>(&raw.x);
    __half2 p1 = *reinterpret_cast<__half2*>(&raw.y);
    float2 f0 = __half22float2(p0), f1 = __half22float2(p1);
    return make_float4(f0.x, f0.y, f1.x, f1.y);
}

// ======================= setup kernels =========================================
__global__ void zero_prep_k(int* deg, float* sum, float* sq, int* flag32,
                            const float* __restrict__ W1a, const float* __restrict__ W1b,
                            const float* __restrict__ W2a, const float* __restrict__ W2b,
                            __half* __restrict__ wt,
                            const float* __restrict__ obj, const float* __restrict__ pred,
                            __half* __restrict__ objh, __half* __restrict__ predh,
                            int O, long no4, long np4)
{
    long i = blockIdx.x * (long)blockDim.x + threadIdx.x;
    if (i == 0) *flag32 = 0;
    if (i < O) { deg[i] = 0; return; }
    i -= O;
    if (i < 4608) {
        if (i < 2304) sum[i] = 0.f; else sq[i - 2304] = 0.f;
        return;
    }
    i -= 4608;
    if (i < WT_TOTAL) {
        const float* W; int K, N; long base;
        if (i < 196608)       { W = W1a; K = 384; N = 512;  base = 0;       }
        else if (i < 786432)  { W = W1b; K = 512; N = 1152; base = 196608;  }
        else if (i < 1048576) { W = W2a; K = 512; N = 512;  base = 786432;  }
        else                  { W = W2b; K = 512; N = 128;  base = 1048576; }
        int j = (int)(i - base);
        int k = j / N, n = j % N;
        wt[base + (long)n * K + k] = __float2half(W[(long)k * N + n]);
        return;
    }
    i -= WT_TOTAL;
    if (i >= no4 + np4) return;
    const float* src; __half* dst; long e0;
    if (i < no4) { src = obj;  dst = objh;  e0 = i * 4; }
    else         { src = pred; dst = predh; e0 = (i - no4) * 4; }
    float4 v = *reinterpret_cast<const float4*>(src + e0);
    __half2 h01 = __floats2half2_rn(v.x, v.y);
    __half2 h23 = __floats2half2_rn(v.z, v.w);
    *reinterpret_cast<uint2*>(dst + e0) =
        make_uint2(*reinterpret_cast<uint32_t*>(&h01), *reinterpret_cast<uint32_t*>(&h23));
}

__global__ void probe_k(const int* __restrict__ e32, int* flag32, int T)
{
    int t = blockIdx.x * blockDim.x + threadIdx.x;
    if (t >= T) return;
    if (e32[2 * t + 1] != 0) atomicOr(flag32, 1);
}

__global__ void convert_k(const int* __restrict__ e32, const int* __restrict__ flag32,
                          int* __restrict__ es, int* __restrict__ eo,
                          int* __restrict__ deg, int T)
{
    int t = blockIdx.x * blockDim.x + threadIdx.x;
    if (t >= T) return;
    int s, o;
    if (*flag32) { s = e32[2 * t]; o = e32[2 * t + 1]; }
    else         { s = e32[4 * t]; o = e32[4 * t + 2]; }
    es[t] = s;
    eo[t] = o;
    atomicAdd(&deg[s], 1);
    atomicAdd(&deg[o], 1);
}

__global__ void scan_k(const int* __restrict__ deg, int* __restrict__ offs,
                       int* __restrict__ cur, int O)
{
    __shared__ int part[1024];
    int tid = threadIdx.x;
    int chunk = (O + 1023) / 1024;
    int b = tid * chunk, e = b + chunk; if (e > O) e = O; if (b > O) b = O;
    int s = 0;
    for (int i = b; i < e; i++) s += deg[i];
    part[tid] = s;
    __syncthreads();
    for (int off = 1; off < 1024; off <<= 1) {
        int v = (tid >= off) ? part[tid - off] : 0;
        __syncthreads();
        part[tid] += v;
        __syncthreads();
    }
    int base = (tid == 0) ? 0 : part[tid - 1];
    for (int i = b; i < e; i++) {
        offs[i] = base;
        cur[i]  = base;
        base += deg[i];
    }
    if (tid == 0) offs[O] = part[1023];
}

__global__ void fill_k(const int* __restrict__ es, const int* __restrict__ eo,
                       int* __restrict__ cur, int* __restrict__ elist, int T)
{
    int t = blockIdx.x * blockDim.x + threadIdx.x;
    if (t >= T) return;
    int p = atomicAdd(&cur[es[t]], 1);
    elist[p] = t * 2;
    int q = atomicAdd(&cur[eo[t]], 1);
    elist[q] = t * 2 + 1;
}

__global__ void bnhalf_k(const float* __restrict__ X,
                         const float* __restrict__ cA, const float* __restrict__ cB,
                         __half* __restrict__ h, long n4, int N)
{
    long i = blockIdx.x * (long)blockDim.x + threadIdx.x;
    if (i >= n4) return;
    long e0 = i * 4;
    int c = (int)(e0 & (N - 1));
    float4 v = *reinterpret_cast<const float4*>(X + e0);
    float4 a = *reinterpret_cast<const float4*>(cA + c);
    float4 b = *reinterpret_cast<const float4*>(cB + c);
    v = bn4(v, a, b);
    __half2 h01 = __floats2half2_rn(v.x, v.y);
    __half2 h23 = __floats2half2_rn(v.z, v.w);
    *reinterpret_cast<uint2*>(h + e0) =
        make_uint2(*reinterpret_cast<uint32_t*>(&h01), *reinterpret_cast<uint32_t*>(&h23));
}

// ======================= pipelined mma.sync GEMM ===============================
// CTA 128x128, 16 warps (4x4), warp tile 32x32, fp16 A/B, fp32 acc.
// 4-stage cp.async (prefetch 3), loads issued BEFORE compute, and
// register double-buffered fragments (ldsm s+1 overlaps mma s).
#define ROWB   144
#define STAGE  (2 * 128 * ROWB)          // 36864 B: A, B
#define NSTG   4
#define GEMM_SMEM (NSTG * STAGE)         // 147456 B

template<bool GATHER, typename TOUT>
__global__ void __launch_bounds__(512, 1)
mma_gemm_k(const __half* __restrict__ Ax,
           const __half* __restrict__ objh, const __half* __restrict__ predh,
           const int* __restrict__ es, const int* __restrict__ eo,
           const __half* __restrict__ Bt,
           const float* __restrict__ bias,
           TOUT* __restrict__ C, float* __restrict__ gsum, float* __restrict__ gsq,
           int M, int N, int K)
{
    extern __shared__ __align__(16) char smem[];
    const uint32_t sbase = smem_to_u32(smem);

    const int tid  = threadIdx.x;
    const int lane = tid & 31;
    const int wid  = tid >> 5;
    const int wm   = wid >> 2;
    const int wn   = wid & 3;
    const int m0   = blockIdx.y * 128, n0 = blockIdx.x * 128;
    const int q8   = lane >> 3;
    const int r8   = lane & 7;

    float acc[2][4][4];
#pragma unroll
    for (int i = 0; i < 2; i++)
#pragma unroll
        for (int j = 0; j < 4; j++)
#pragma unroll
            for (int q = 0; q < 4; q++) acc[i][j][q] = 0.f;

    const int nk = K >> 6;

    auto load_chunk = [&](int k0, int stage) {
        const uint32_t aA = sbase + stage * STAGE;
        const uint32_t aB = aA + 128 * ROWB;
#pragma unroll
        for (int i = 0; i < 2; i++) {
            int idx = tid + (i << 9);
            int r   = (idx >> 3) & 127;
            int c   = idx & 7;
            int gm  = m0 + r;
            int gmc = gm < M ? gm : M - 1;
            const __half* src;
            if (GATHER) {
                long sr; const __half* sh;
                if (k0 < 128)      { sr = (long)es[gmc]; sh = objh;  }
                else if (k0 < 256) { sr = gmc;           sh = predh; }
                else               { sr = (long)eo[gmc]; sh = objh;  }
                src = sh + sr * 128 + (k0 & 127) + c * 8;
            } else {
                src = Ax + (long)gmc * K + k0 + c * 8;
            }
            cp16(aA + r * ROWB + c * 16, src);
        }
#pragma unroll
        for (int i = 0; i < 2; i++) {
            int idx = tid + (i << 9);
            int r   = (idx >> 3) & 127;
            int c   = idx & 7;
            const __half* src = Bt + (long)(n0 + r) * K + k0 + c * 8;
            cp16(aB + r * ROWB + c * 16, src);
        }
        CP_COMMIT();
    };

    auto compute = [&](int stage) {
        const uint32_t aA = sbase + stage * STAGE;
        const uint32_t aB = aA + 128 * ROWB;
        uint32_t bh[2][4][2], ah[2][2][4];

        auto ldfrag = [&](int s, int buf) {
#pragma unroll
            for (int j = 0; j < 2; j++) {
                int nrow = wn * 32 + j * 16 + (q8 >> 1) * 8 + r8;
                int kb   = s * 32 + (q8 & 1) * 16;
                uint32_t addr = (uint32_t)(nrow * ROWB + kb);
                uint32_t r[4];
                ldsm_x4(aB + addr, r);
                bh[buf][2 * j][0] = r[0]; bh[buf][2 * j][1] = r[1];
                bh[buf][2 * j + 1][0] = r[2]; bh[buf][2 * j + 1][1] = r[3];
            }
#pragma unroll
            for (int mt = 0; mt < 2; mt++) {
                int mrow = wm * 32 + mt * 16 + (q8 & 1) * 8 + r8;
                int kb   = s * 32 + (q8 >> 1) * 16;
                ldsm_x4(aA + (uint32_t)(mrow * ROWB + kb), ah[buf][mt]);
            }
        };

        ldfrag(0, 0);
#pragma unroll
        for (int s = 0; s < 4; s++) {
            int cur = s & 1;
            if (s < 3) ldfrag(s + 1, cur ^ 1);   // overlap next ldsm with mma
#pragma unroll
            for (int mt = 0; mt < 2; mt++)
#pragma unroll
                for (int nt = 0; nt < 4; nt++)
                    mma_f16(acc[mt][nt], ah[cur][mt], bh[cur][nt]);
        }
    };

    // prefetch 3 chunks
    load_chunk(0, 0);
    if (nk > 1) load_chunk(64, 1);
    if (nk > 2) load_chunk(128, 2);
    for (int it = 0; it < nk; it++) {
        int rem = nk - 1 - it;
        if (rem >= 2)      { CP_WAIT(2); }
        else if (rem == 1) { CP_WAIT(1); }
        else               { CP_WAIT(0); }
        __syncthreads();
        if (it + 3 < nk) load_chunk((it + 3) << 6, (it + 3) & (NSTG - 1));
        compute(it & (NSTG - 1));
    }

    // ---- epilogue: +bias, store, fused column stats ----
#pragma unroll
    for (int nt = 0; nt < 4; nt++) {
        int col = n0 + wn * 32 + nt * 8 + (lane & 3) * 2;
        float2 bv = *reinterpret_cast<const float2*>(bias + col);
        float s0 = 0.f, s1 = 0.f, q0 = 0.f, q1 = 0.f;
#pragma unroll
        for (int mt = 0; mt < 2; mt++) {
            int row0 = m0 + wm * 32 + mt * 16 + (lane >> 2);
            int row1 = row0 + 8;
            float v0 = acc[mt][nt][0] + bv.x;
            float v1 = acc[mt][nt][1] + bv.y;
            float v2 = acc[mt][nt][2] + bv.x;
            float v3 = acc[mt][nt][3] + bv.y;
            if (row0 < M) {
                store2(C, (long)row0 * N + col, v0, v1);
                s0 += v0; q0 += v0 * v0; s1 += v1; q1 += v1 * v1;
            }
            if (row1 < M) {
                store2(C, (long)row1 * N + col, v2, v3);
                s0 += v2; q0 += v2 * v2; s1 += v3; q1 += v3 * v3;
            }
        }
#pragma unroll
        for (int off = 4; off < 32; off <<= 1) {
            s0 += __shfl_down_sync(0xffffffffu, s0, off);
            s1 += __shfl_down_sync(0xffffffffu, s1, off);
            q0 += __shfl_down_sync(0xffffffffu, q0, off);
            q1 += __shfl_down_sync(0xffffffffu, q1, off);
        }
        if (lane < 4) {
            atomicAdd(&gsum[col],     s0);
            atomicAdd(&gsum[col + 1], s1);
            atomicAdd(&gsq[col],      q0);
            atomicAdd(&gsq[col + 1],  q1);
        }
    }
}

// ======================= stats finalize / BN out ==============================
__global__ void finalize_k(const float* __restrict__ sum, const float* __restrict__ sq,
                           const float* __restrict__ gamma, const float* __restrict__ beta,
                           float invM, int N,
                           float* __restrict__ cA, float* __restrict__ cB)
{
    int n = blockIdx.x * blockDim.x + threadIdx.x;
    if (n >= N) return;
    float mean = sum[n] * invM;
    float var  = sq[n] * invM - mean * mean;
    float inv  = rsqrtf(var + EPS);
    float a    = inv * gamma[n];
    cA[n] = a;
    cB[n] = beta[n] - mean * a;
}

__global__ void bn_out_k(const float* __restrict__ X, const float* __restrict__ cA,
                         const float* __restrict__ cB, float* __restrict__ out,
                         long total, int N)
{
    long i = blockIdx.x * (long)blockDim.x + threadIdx.x;
    if (i >= total) return;
    int n = (int)(i % N);
    float v = X[i] * cA[n] + cB[n];
    out[i] = (v >= 0.f) ? v : ALPHA * v;
}

// ======================= CSR pooling ==========================================
__global__ void pool_k(const __half* __restrict__ A2,
                       const float* __restrict__ cA, const float* __restrict__ cB,
                       const int* __restrict__ offs, const int* __restrict__ elist,
                       __half* __restrict__ xh, int O, float ocap)
{
    int b = blockIdx.x;
    if (b >= O) return;
    int tid = threadIdx.x;
    int d0 = offs[b], d1 = offs[b + 1];
    float4 acc = make_float4(0.f, 0.f, 0.f, 0.f);
    for (int e = d0; e < d1; e++) {
        int code = elist[e];
        int t = code >> 1;
        int cb = (code & 1) ? 640 : 0;
        int c  = cb + tid * 4;
        float4 a = *reinterpret_cast<const float4*>(cA + c);
        float4 bb = *reinterpret_cast<const float4*>(cB + c);
        float4 v = bn4(ld_h4(A2 + (long)t * 1152 + c), a, bb);
        acc.x += v.x; acc.y += v.y; acc.z += v.z; acc.w += v.w;
    }
    float c = fminf(fmaxf((float)(d1 - d0), 1.f), ocap);
    float r = 1.f / c;
    __half2 h01 = __floats2half2_rn(acc.x * r, acc.y * r);
    __half2 h23 = __floats2half2_rn(acc.z * r, acc.w * r);
    *reinterpret_cast<uint2*>(xh + (long)b * 512 + tid * 4) =
        make_uint2(*reinterpret_cast<uint32_t*>(&h01), *reinterpret_cast<uint32_t*>(&h23));
}

__global__ void outp_k(const __half* __restrict__ A2,
                       const float* __restrict__ cA, const float* __restrict__ cB,
                       float* __restrict__ out_p, int T)
{
    int idx = blockIdx.x * blockDim.x + threadIdx.x;
    int t = idx >> 5, lane = idx & 31;
    if (t >= T) return;
    int c = 512 + lane * 4;
    float4 a = *reinterpret_cast<const float4*>(cA + c);
    float4 bb = *reinterpret_cast<const float4*>(cB + c);
    float4 v = bn4(ld_h4(A2 + (long)t * 1152 + c), a, bb);
    *reinterpret_cast<float4*>(out_p + (long)t * 128 + lane * 4) = v;
}

// ======================= launch ================================================
extern "C" void kernel_launch(void* const* d_in, const int* in_sizes, int n_in,
                              void* d_out, int out_size)
{
    const float* obj   = (const float*)d_in[0];
    const float* pred  = (const float*)d_in[1];
    const int*   e32   = (const int*)d_in[2];
    const float* W1a = (const float*)d_in[3];
    const float* b1a = (const float*)d_in[4];
    const float* g1a = (const float*)d_in[5];
    const float* be1a= (const float*)d_in[6];
    const float* W1b = (const float*)d_in[7];
    const float* b1b = (const float*)d_in[8];
    const float* g1b = (const float*)d_in[9];
    const float* be1b= (const float*)d_in[10];
    const float* W2a = (const float*)d_in[11];
    const float* b2a = (const float*)d_in[12];
    const float* g2a = (const float*)d_in[13];
    const float* be2a= (const float*)d_in[14];
    const float* W2b = (const float*)d_in[15];
    const float* b2b = (const float*)d_in[16];
    const float* g2b = (const float*)d_in[17];
    const float* be2b= (const float*)d_in[18];

    const int O = in_sizes[0] / 128;
    const int T = in_sizes[1] / 128;

    float* out     = (float*)d_out;
    float* out_obj = out;
    float* out_p   = out + (size_t)O * 128;

    float *A1, *A4, *SUM, *SQ, *CA, *CB;
    __half *A2;
    int *ES, *EO, *FLAG, *DEG, *OFFS, *CUR, *ELIST;
    __half *WT, *OBJH, *PRH, *XH;
    cudaGetSymbolAddress((void**)&A1,    g_A1);
    cudaGetSymbolAddress((void**)&A2,    g_A2);
    cudaGetSymbolAddress((void**)&A4,    g_A4);
    cudaGetSymbolAddress((void**)&SUM,   g_sum);
    cudaGetSymbolAddress((void**)&SQ,    g_sq);
    cudaGetSymbolAddress((void**)&CA,    g_cA);
    cudaGetSymbolAddress((void**)&CB,    g_cB);
    cudaGetSymbolAddress((void**)&ES,    g_es);
    cudaGetSymbolAddress((void**)&EO,    g_eo);
    cudaGetSymbolAddress((void**)&FLAG,  g_flag32);
    cudaGetSymbolAddress((void**)&DEG,   g_deg);
    cudaGetSymbolAddress((void**)&OFFS,  g_off);
    cudaGetSymbolAddress((void**)&CUR,   g_cur);
    cudaGetSymbolAddress((void**)&ELIST, g_elist);
    cudaGetSymbolAddress((void**)&WT,    g_wt);
    cudaGetSymbolAddress((void**)&OBJH,  g_objh);
    cudaGetSymbolAddress((void**)&PRH,   g_predh);
    cudaGetSymbolAddress((void**)&XH,    g_xh);

    cudaFuncSetAttribute(mma_gemm_k<true,  float>,
                         cudaFuncAttributeMaxDynamicSharedMemorySize, GEMM_SMEM);
    cudaFuncSetAttribute(mma_gemm_k<false, __half>,
                         cudaFuncAttributeMaxDynamicSharedMemorySize, GEMM_SMEM);
    cudaFuncSetAttribute(mma_gemm_k<false, float>,
                         cudaFuncAttributeMaxDynamicSharedMemorySize, GEMM_SMEM);

    const int OFF1 = 0, OFF2 = 512, OFF3 = 1664, OFF4 = 2176;
    const int W1A_OFF = 0, W1B_OFF = 196608, W2A_OFF = 786432, W2B_OFF = 1048576;

    const long no4 = (long)O * 32, np4 = (long)T * 32;
    const long prep_total = (long)O + 4608 + WT_TOTAL + no4 + np4;

    zero_prep_k<<<(unsigned)((prep_total + 255) / 256), 256>>>(
        DEG, SUM, SQ, FLAG, W1a, W1b, W2a, W2b, WT,
        obj, pred, OBJH, PRH, O, no4, np4);
    probe_k<<<(T + 255) / 256, 256>>>(e32, FLAG, T);
    convert_k<<<(T + 255) / 256, 256>>>(e32, FLAG, ES, EO, DEG, T);

    // launch 3: GEMM1 (gathered)  <-- ncu capture slot
    mma_gemm_k<true, float><<<dim3(4, (T + 127) / 128), 512, GEMM_SMEM>>>(
        nullptr, OBJH, PRH, ES, EO, WT + W1A_OFF, b1a,
        A1, SUM + OFF1, SQ + OFF1, T, 512, 384);
    finalize_k<<<2, 256>>>(SUM + OFF1, SQ + OFF1, g1a, be1a, 1.f / T, 512, CA + OFF1, CB + OFF1);

    bnhalf_k<<<(unsigned)(((long)T * 128 + 255) / 256), 256>>>(
        A1, CA + OFF1, CB + OFF1, XH, (long)T * 128, 512);
    scan_k<<<1, 1024>>>(DEG, OFFS, CUR, O);
    fill_k<<<(T + 255) / 256, 256>>>(ES, EO, CUR, ELIST, T);

    mma_gemm_k<false, __half><<<dim3(9, (T + 127) / 128), 512, GEMM_SMEM>>>(
        XH, nullptr, nullptr, nullptr, nullptr, WT + W1B_OFF, b1b,
        A2, SUM + OFF2, SQ + OFF2, T, 1152, 512);
    finalize_k<<<5, 256>>>(SUM + OFF2, SQ + OFF2, g1b, be1b, 1.f / T, 1152, CA + OFF2, CB + OFF2);

    pool_k<<<O, 128>>>(A2, CA + OFF2, CB + OFF2, OFFS, ELIST, XH, O, (float)O);
    outp_k<<<(T * 32 + 255) / 256, 256>>>(A2, CA + OFF2, CB + OFF2, out_p, T);

    mma_gemm_k<false, float><<<dim3(4, (O + 127) / 128), 512, GEMM_SMEM>>>(
        XH, nullptr, nullptr, nullptr, nullptr, WT + W2A_OFF, b2a,
        A1, SUM + OFF3, SQ + OFF3, O, 512, 512);
    finalize_k<<<2, 256>>>(SUM + OFF3, SQ + OFF3, g2a, be2a, 1.f / O, 512, CA + OFF3, CB + OFF3);

    bnhalf_k<<<(unsigned)(((long)O * 128 + 255) / 256), 256>>>(
        A1, CA + OFF3, CB + OFF3, XH, (long)O * 128, 512);

    mma_gemm_k<false, float><<<dim3(1, (O + 127) / 128), 512, GEMM_SMEM>>>(
        XH, nullptr, nullptr, nullptr, nullptr, WT + W2B_OFF, b2b,
        A4, SUM + OFF4, SQ + OFF4, O, 128, 512);
    finalize_k<<<1, 256>>>(SUM + OFF4, SQ + OFF4, g2b, be2b, 1.f / O, 128, CA + OFF4, CB + OFF4);

    bn_out_k<<<(unsigned)(((long)O * 128 + 255) / 256), 256>>>(
        A4, CA + OFF4, CB + OFF4, out_obj, (long)O * 128, 128);
}

// round 17
// speedup vs baseline: 1.0830x; 1.0830x over previous
#include <cuda_runtime.h>
#include <cuda_fp16.h>
#include <cstdint>

#define EPS    1e-5f
#define ALPHA  0.2f
#define MAX_O  50000
#define MAX_T  200000

// ---------------- scratch (static device globals; no allocation) -------------
__device__ float  g_A1[(size_t)MAX_T * 512];
__device__ __half g_A2[(size_t)MAX_T * 1152];
__device__ float  g_A4[(size_t)MAX_O * 128];
__device__ int    g_deg[MAX_O];
__device__ int    g_off[MAX_O + 1];
__device__ int    g_cur[MAX_O];
__device__ int    g_elist[2 * MAX_T];
__device__ int    g_es[MAX_T];
__device__ int    g_eo[MAX_T];
__device__ int    g_flag32;
__device__ __half g_objh[(size_t)MAX_O * 128];
__device__ __half g_predh[(size_t)MAX_T * 128];
__device__ __half g_xh[(size_t)MAX_T * 512];
#define WT_TOTAL 1114112
__device__ __half g_wt[WT_TOTAL];
__device__ float g_sum[2304];
__device__ float g_sq[2304];
__device__ float g_cA[2304];
__device__ float g_cB[2304];

// ======================= PTX wrappers =========================================
__device__ __forceinline__ uint32_t smem_to_u32(const void* p) {
    uint32_t a;
    asm("{ .reg .u64 t; cvta.to.shared.u64 t, %1; cvt.u32.u64 %0, t; }" : "=r"(a) : "l"(p));
    return a;
}
__device__ __forceinline__ void ldsm_x4(uint32_t addr, uint32_t* r) {
    asm volatile("ldmatrix.sync.aligned.m8n8.x4.shared.b16 {%0,%1,%2,%3}, [%4];"
        : "=r"(r[0]), "=r"(r[1]), "=r"(r[2]), "=r"(r[3]) : "r"(addr));
}
__device__ __forceinline__ void mma_f16(float* c, const uint32_t* a, const uint32_t* b) {
    asm volatile("mma.sync.aligned.m16n8k16.row.col.f32.f16.f16.f32 "
        "{%0,%1,%2,%3},{%4,%5,%6,%7},{%8,%9},{%0,%1,%2,%3};"
        : "+f"(c[0]), "+f"(c[1]), "+f"(c[2]), "+f"(c[3])
        : "r"(a[0]), "r"(a[1]), "r"(a[2]), "r"(a[3]), "r"(b[0]), "r"(b[1]));
}
__device__ __forceinline__ void cp16(uint32_t dst, const void* src) {
    asm volatile("cp.async.cg.shared.global [%0], [%1], 16;" :: "r"(dst), "l"(src));
}
#define CP_COMMIT() asm volatile("cp.async.commit_group;" ::: "memory")
#define CP_WAIT(n)  asm volatile("cp.async.wait_group %0;" :: "n"(n) : "memory")

__device__ __forceinline__ void store2(float* C, long off, float v0, float v1) {
    *reinterpret_cast<float2*>(C + off) = make_float2(v0, v1);
}
__device__ __forceinline__ void store2(__half* C, long off, float v0, float v1) {
    *reinterpret_cast<__half2*>(C + off) = __floats2half2_rn(v0, v1);
}

__device__ __forceinline__ float4 bn4(float4 v, float4 a, float4 b) {
    v.x = fmaf(v.x, a.x, b.x); v.x = v.x >= 0.f ? v.x : ALPHA * v.x;
    v.y = fmaf(v.y, a.y, b.y); v.y = v.y >= 0.f ? v.y : ALPHA * v.y;
    v.z = fmaf(v.z, a.z, b.z); v.z = v.z >= 0.f ? v.z : ALPHA * v.z;
    v.w = fmaf(v.w, a.w, b.w); v.w = v.w >= 0.f ? v.w : ALPHA * v.w;
    return v;
}
__device__ __forceinline__ float4 ld_h4(const __half* p) {
    uint2 raw = *reinterpret_cast<const uint2*>(p);
    __half2 p0 = *reinterpret_cast<__half2*>(&raw.x);
    __half2 p1 = *reinterpret_cast<__half2*>(&raw.y);
    float2 f0 = __half22float2(p0), f1 = __half22float2(p1);
    return make_float4(f0.x, f0.y, f1.x, f1.y);
}

// ======================= setup kernels =========================================
__global__ void zero_prep_k(int* deg, float* sum, float* sq, int* flag32,
                            const float* __restrict__ W1a, const float* __restrict__ W1b,
                            const float* __restrict__ W2a, const float* __restrict__ W2b,
                            __half* __restrict__ wt,
                            const float* __restrict__ obj, const float* __restrict__ pred,
                            __half* __restrict__ objh, __half* __restrict__ predh,
                            int O, long no4, long np4)
{
    long i = blockIdx.x * (long)blockDim.x + threadIdx.x;
    if (i == 0) *flag32 = 0;
    if (i < O) { deg[i] = 0; return; }
    i -= O;
    if (i < 4608) {
        if (i < 2304) sum[i] = 0.f; else sq[i - 2304] = 0.f;
        return;
    }
    i -= 4608;
    if (i < WT_TOTAL) {
        const float* W; int K, N; long base;
        if (i < 196608)       { W = W1a; K = 384; N = 512;  base = 0;       }
        else if (i < 786432)  { W = W1b; K = 512; N = 1152; base = 196608;  }
        else if (i < 1048576) { W = W2a; K = 512; N = 512;  base = 786432;  }
        else                  { W = W2b; K = 512; N = 128;  base = 1048576; }
        int j = (int)(i - base);
        int k = j / N, n = j % N;
        wt[base + (long)n * K + k] = __float2half(W[(long)k * N + n]);
        return;
    }
    i -= WT_TOTAL;
    if (i >= no4 + np4) return;
    const float* src; __half* dst; long e0;
    if (i < no4) { src = obj;  dst = objh;  e0 = i * 4; }
    else         { src = pred; dst = predh; e0 = (i - no4) * 4; }
    float4 v = *reinterpret_cast<const float4*>(src + e0);
    __half2 h01 = __floats2half2_rn(v.x, v.y);
    __half2 h23 = __floats2half2_rn(v.z, v.w);
    *reinterpret_cast<uint2*>(dst + e0) =
        make_uint2(*reinterpret_cast<uint32_t*>(&h01), *reinterpret_cast<uint32_t*>(&h23));
}

__global__ void probe_k(const int* __restrict__ e32, int* flag32, int T)
{
    int t = blockIdx.x * blockDim.x + threadIdx.x;
    if (t >= T) return;
    if (e32[2 * t + 1] != 0) atomicOr(flag32, 1);
}

__global__ void convert_k(const int* __restrict__ e32, const int* __restrict__ flag32,
                          int* __restrict__ es, int* __restrict__ eo,
                          int* __restrict__ deg, int T)
{
    int t = blockIdx.x * blockDim.x + threadIdx.x;
    if (t >= T) return;
    int s, o;
    if (*flag32) { s = e32[2 * t]; o = e32[2 * t + 1]; }
    else         { s = e32[4 * t]; o = e32[4 * t + 2]; }
    es[t] = s;
    eo[t] = o;
    atomicAdd(&deg[s], 1);
    atomicAdd(&deg[o], 1);
}

__global__ void scan_k(const int* __restrict__ deg, int* __restrict__ offs,
                       int* __restrict__ cur, int O)
{
    __shared__ int part[1024];
    int tid = threadIdx.x;
    int chunk = (O + 1023) / 1024;
    int b = tid * chunk, e = b + chunk; if (e > O) e = O; if (b > O) b = O;
    int s = 0;
    for (int i = b; i < e; i++) s += deg[i];
    part[tid] = s;
    __syncthreads();
    for (int off = 1; off < 1024; off <<= 1) {
        int v = (tid >= off) ? part[tid - off] : 0;
        __syncthreads();
        part[tid] += v;
        __syncthreads();
    }
    int base = (tid == 0) ? 0 : part[tid - 1];
    for (int i = b; i < e; i++) {
        offs[i] = base;
        cur[i]  = base;
        base += deg[i];
    }
    if (tid == 0) offs[O] = part[1023];
}

__global__ void fill_k(const int* __restrict__ es, const int* __restrict__ eo,
                       int* __restrict__ cur, int* __restrict__ elist, int T)
{
    int t = blockIdx.x * blockDim.x + threadIdx.x;
    if (t >= T) return;
    int p = atomicAdd(&cur[es[t]], 1);
    elist[p] = t * 2;
    int q = atomicAdd(&cur[eo[t]], 1);
    elist[q] = t * 2 + 1;
}

__global__ void bnhalf_k(const float* __restrict__ X,
                         const float* __restrict__ cA, const float* __restrict__ cB,
                         __half* __restrict__ h, long n4, int N)
{
    long i = blockIdx.x * (long)blockDim.x + threadIdx.x;
    if (i >= n4) return;
    long e0 = i * 4;
    int c = (int)(e0 & (N - 1));
    float4 v = *reinterpret_cast<const float4*>(X + e0);
    float4 a = *reinterpret_cast<const float4*>(cA + c);
    float4 b = *reinterpret_cast<const float4*>(cB + c);
    v = bn4(v, a, b);
    __half2 h01 = __floats2half2_rn(v.x, v.y);
    __half2 h23 = __floats2half2_rn(v.z, v.w);
    *reinterpret_cast<uint2*>(h + e0) =
        make_uint2(*reinterpret_cast<uint32_t*>(&h01), *reinterpret_cast<uint32_t*>(&h23));
}

// ======================= pipelined mma.sync GEMM ===============================
// CTA tile 64x128, 256 threads (8 warps, 2m x 4n), warp tile 32x32.
// 4-stage cp.async, prefetch 3. 2 CTAs/SM -> cross-CTA latency hiding.
#define ROWB    144
#define A_ROWS  64
#define STAGE   ((A_ROWS + 128) * ROWB)   // 27648 B
#define NSTG    4
#define GEMM_SMEM (NSTG * STAGE)          // 110592 B (2 CTAs/SM)

template<bool GATHER, typename TOUT>
__global__ void __launch_bounds__(256, 2)
mma_gemm_k(const __half* __restrict__ Ax,
           const __half* __restrict__ objh, const __half* __restrict__ predh,
           const int* __restrict__ es, const int* __restrict__ eo,
           const __half* __restrict__ Bt,
           const float* __restrict__ bias,
           TOUT* __restrict__ C, float* __restrict__ gsum, float* __restrict__ gsq,
           int M, int N, int K)
{
    extern __shared__ __align__(16) char smem[];
    const uint32_t sbase = smem_to_u32(smem);

    const int tid  = threadIdx.x;
    const int lane = tid & 31;
    const int wid  = tid >> 5;
    const int wm   = wid >> 2;            // 0..1 (32-row slabs)
    const int wn   = wid & 3;             // 0..3 (32-col slabs)
    const int m0   = blockIdx.y * A_ROWS, n0 = blockIdx.x * 128;
    const int q8   = lane >> 3;
    const int r8   = lane & 7;

    float acc[2][4][4];
#pragma unroll
    for (int i = 0; i < 2; i++)
#pragma unroll
        for (int j = 0; j < 4; j++)
#pragma unroll
            for (int q = 0; q < 4; q++) acc[i][j][q] = 0.f;

    const int nk = K >> 6;

    auto load_chunk = [&](int k0, int stage) {
        const uint32_t aA = sbase + stage * STAGE;
        const uint32_t aB = aA + A_ROWS * ROWB;
        // A: 64 rows x 8 chunks of 16B = 512 cp16 / 256 thr = 2
#pragma unroll
        for (int i = 0; i < 2; i++) {
            int idx = tid + (i << 8);
            int r   = (idx >> 3) & 63;
            int c   = idx & 7;
            int gm  = m0 + r;
            int gmc = gm < M ? gm : M - 1;
            const __half* src;
            if (GATHER) {
                long sr; const __half* sh;
                if (k0 < 128)      { sr = (long)es[gmc]; sh = objh;  }
                else if (k0 < 256) { sr = gmc;           sh = predh; }
                else               { sr = (long)eo[gmc]; sh = objh;  }
                src = sh + sr * 128 + (k0 & 127) + c * 8;
            } else {
                src = Ax + (long)gmc * K + k0 + c * 8;
            }
            cp16(aA + r * ROWB + c * 16, src);
        }
        // B: 128 rows x 8 chunks of 16B = 1024 cp16 / 256 thr = 4
#pragma unroll
        for (int i = 0; i < 4; i++) {
            int idx = tid + (i << 8);
            int r   = (idx >> 3) & 127;
            int c   = idx & 7;
            const __half* src = Bt + (long)(n0 + r) * K + k0 + c * 8;
            cp16(aB + r * ROWB + c * 16, src);
        }
        CP_COMMIT();
    };

    auto compute = [&](int stage) {
        const uint32_t aA = sbase + stage * STAGE;
        const uint32_t aB = aA + A_ROWS * ROWB;
#pragma unroll
        for (int s = 0; s < 4; s++) {
            uint32_t bh[4][2], ah[2][4];
#pragma unroll
            for (int j = 0; j < 2; j++) {
                int nrow = wn * 32 + j * 16 + (q8 >> 1) * 8 + r8;
                int kb   = s * 32 + (q8 & 1) * 16;
                uint32_t addr = (uint32_t)(nrow * ROWB + kb);
                uint32_t r[4];
                ldsm_x4(aB + addr, r);
                bh[2 * j][0] = r[0]; bh[2 * j][1] = r[1];
                bh[2 * j + 1][0] = r[2]; bh[2 * j + 1][1] = r[3];
            }
#pragma unroll
            for (int mt = 0; mt < 2; mt++) {
                int mrow = wm * 32 + mt * 16 + (q8 & 1) * 8 + r8;
                int kb   = s * 32 + (q8 >> 1) * 16;
                ldsm_x4(aA + (uint32_t)(mrow * ROWB + kb), ah[mt]);
            }
#pragma unroll
            for (int mt = 0; mt < 2; mt++)
#pragma unroll
                for (int nt = 0; nt < 4; nt++)
                    mma_f16(acc[mt][nt], ah[mt], bh[nt]);
        }
    };

    load_chunk(0, 0);
    if (nk > 1) load_chunk(64, 1);
    if (nk > 2) load_chunk(128, 2);
    for (int it = 0; it < nk; it++) {
        int rem = nk - 1 - it;
        if (rem >= 2)      { CP_WAIT(2); }
        else if (rem == 1) { CP_WAIT(1); }
        else               { CP_WAIT(0); }
        __syncthreads();
        if (it + 3 < nk) load_chunk((it + 3) << 6, (it + 3) & (NSTG - 1));
        compute(it & (NSTG - 1));
    }

    // ---- epilogue: +bias, store, fused column stats ----
#pragma unroll
    for (int nt = 0; nt < 4; nt++) {
        int col = n0 + wn * 32 + nt * 8 + (lane & 3) * 2;
        float2 bv = *reinterpret_cast<const float2*>(bias + col);
        float s0 = 0.f, s1 = 0.f, q0 = 0.f, q1 = 0.f;
#pragma unroll
        for (int mt = 0; mt < 2; mt++) {
            int row0 = m0 + wm * 32 + mt * 16 + (lane >> 2);
            int row1 = row0 + 8;
            float v0 = acc[mt][nt][0] + bv.x;
            float v1 = acc[mt][nt][1] + bv.y;
            float v2 = acc[mt][nt][2] + bv.x;
            float v3 = acc[mt][nt][3] + bv.y;
            if (row0 < M) {
                store2(C, (long)row0 * N + col, v0, v1);
                s0 += v0; q0 += v0 * v0; s1 += v1; q1 += v1 * v1;
            }
            if (row1 < M) {
                store2(C, (long)row1 * N + col, v2, v3);
                s0 += v2; q0 += v2 * v2; s1 += v3; q1 += v3 * v3;
            }
        }
#pragma unroll
        for (int off = 4; off < 32; off <<= 1) {
            s0 += __shfl_down_sync(0xffffffffu, s0, off);
            s1 += __shfl_down_sync(0xffffffffu, s1, off);
            q0 += __shfl_down_sync(0xffffffffu, q0, off);
            q1 += __shfl_down_sync(0xffffffffu, q1, off);
        }
        if (lane < 4) {
            atomicAdd(&gsum[col],     s0);
            atomicAdd(&gsum[col + 1], s1);
            atomicAdd(&gsq[col],      q0);
            atomicAdd(&gsq[col + 1],  q1);
        }
    }
}

// ======================= stats finalize / BN out ==============================
__global__ void finalize_k(const float* __restrict__ sum, const float* __restrict__ sq,
                           const float* __restrict__ gamma, const float* __restrict__ beta,
                           float invM, int N,
                           float* __restrict__ cA, float* __restrict__ cB)
{
    int n = blockIdx.x * blockDim.x + threadIdx.x;
    if (n >= N) return;
    float mean = sum[n] * invM;
    float var  = sq[n] * invM - mean * mean;
    float inv  = rsqrtf(var + EPS);
    float a    = inv * gamma[n];
    cA[n] = a;
    cB[n] = beta[n] - mean * a;
}

__global__ void bn_out_k(const float* __restrict__ X, const float* __restrict__ cA,
                         const float* __restrict__ cB, float* __restrict__ out,
                         long total, int N)
{
    long i = blockIdx.x * (long)blockDim.x + threadIdx.x;
    if (i >= total) return;
    int n = (int)(i % N);
    float v = X[i] * cA[n] + cB[n];
    out[i] = (v >= 0.f) ? v : ALPHA * v;
}

// ======================= CSR pooling ==========================================
__global__ void pool_k(const __half* __restrict__ A2,
                       const float* __restrict__ cA, const float* __restrict__ cB,
                       const int* __restrict__ offs, const int* __restrict__ elist,
                       __half* __restrict__ xh, int O, float ocap)
{
    int b = blockIdx.x;
    if (b >= O) return;
    int tid = threadIdx.x;
    int d0 = offs[b], d1 = offs[b + 1];
    float4 acc = make_float4(0.f, 0.f, 0.f, 0.f);
    for (int e = d0; e < d1; e++) {
        int code = elist[e];
        int t = code >> 1;
        int cb = (code & 1) ? 640 : 0;
        int c  = cb + tid * 4;
        float4 a = *reinterpret_cast<const float4*>(cA + c);
        float4 bb = *reinterpret_cast<const float4*>(cB + c);
        float4 v = bn4(ld_h4(A2 + (long)t * 1152 + c), a, bb);
        acc.x += v.x; acc.y += v.y; acc.z += v.z; acc.w += v.w;
    }
    float c = fminf(fmaxf((float)(d1 - d0), 1.f), ocap);
    float r = 1.f / c;
    __half2 h01 = __floats2half2_rn(acc.x * r, acc.y * r);
    __half2 h23 = __floats2half2_rn(acc.z * r, acc.w * r);
    *reinterpret_cast<uint2*>(xh + (long)b * 512 + tid * 4) =
        make_uint2(*reinterpret_cast<uint32_t*>(&h01), *reinterpret_cast<uint32_t*>(&h23));
}

__global__ void outp_k(const __half* __restrict__ A2,
                       const float* __restrict__ cA, const float* __restrict__ cB,
                       float* __restrict__ out_p, int T)
{
    int idx = blockIdx.x * blockDim.x + threadIdx.x;
    int t = idx >> 5, lane = idx & 31;
    if (t >= T) return;
    int c = 512 + lane * 4;
    float4 a = *reinterpret_cast<const float4*>(cA + c);
    float4 bb = *reinterpret_cast<const float4*>(cB + c);
    float4 v = bn4(ld_h4(A2 + (long)t * 1152 + c), a, bb);
    *reinterpret_cast<float4*>(out_p + (long)t * 128 + lane * 4) = v;
}

// ======================= launch ================================================
extern "C" void kernel_launch(void* const* d_in, const int* in_sizes, int n_in,
                              void* d_out, int out_size)
{
    const float* obj   = (const float*)d_in[0];
    const float* pred  = (const float*)d_in[1];
    const int*   e32   = (const int*)d_in[2];
    const float* W1a = (const float*)d_in[3];
    const float* b1a = (const float*)d_in[4];
    const float* g1a = (const float*)d_in[5];
    const float* be1a= (const float*)d_in[6];
    const float* W1b = (const float*)d_in[7];
    const float* b1b = (const float*)d_in[8];
    const float* g1b = (const float*)d_in[9];
    const float* be1b= (const float*)d_in[10];
    const float* W2a = (const float*)d_in[11];
    const float* b2a = (const float*)d_in[12];
    const float* g2a = (const float*)d_in[13];
    const float* be2a= (const float*)d_in[14];
    const float* W2b = (const float*)d_in[15];
    const float* b2b = (const float*)d_in[16];
    const float* g2b = (const float*)d_in[17];
    const float* be2b= (const float*)d_in[18];

    const int O = in_sizes[0] / 128;
    const int T = in_sizes[1] / 128;

    float* out     = (float*)d_out;
    float* out_obj = out;
    float* out_p   = out + (size_t)O * 128;

    float *A1, *A4, *SUM, *SQ, *CA, *CB;
    __half *A2;
    int *ES, *EO, *FLAG, *DEG, *OFFS, *CUR, *ELIST;
    __half *WT, *OBJH, *PRH, *XH;
    cudaGetSymbolAddress((void**)&A1,    g_A1);
    cudaGetSymbolAddress((void**)&A2,    g_A2);
    cudaGetSymbolAddress((void**)&A4,    g_A4);
    cudaGetSymbolAddress((void**)&SUM,   g_sum);
    cudaGetSymbolAddress((void**)&SQ,    g_sq);
    cudaGetSymbolAddress((void**)&CA,    g_cA);
    cudaGetSymbolAddress((void**)&CB,    g_cB);
    cudaGetSymbolAddress((void**)&ES,    g_es);
    cudaGetSymbolAddress((void**)&EO,    g_eo);
    cudaGetSymbolAddress((void**)&FLAG,  g_flag32);
    cudaGetSymbolAddress((void**)&DEG,   g_deg);
    cudaGetSymbolAddress((void**)&OFFS,  g_off);
    cudaGetSymbolAddress((void**)&CUR,   g_cur);
    cudaGetSymbolAddress((void**)&ELIST, g_elist);
    cudaGetSymbolAddress((void**)&WT,    g_wt);
    cudaGetSymbolAddress((void**)&OBJH,  g_objh);
    cudaGetSymbolAddress((void**)&PRH,   g_predh);
    cudaGetSymbolAddress((void**)&XH,    g_xh);

    cudaFuncSetAttribute(mma_gemm_k<true,  float>,
                         cudaFuncAttributeMaxDynamicSharedMemorySize, GEMM_SMEM);
    cudaFuncSetAttribute(mma_gemm_k<false, __half>,
                         cudaFuncAttributeMaxDynamicSharedMemorySize, GEMM_SMEM);
    cudaFuncSetAttribute(mma_gemm_k<false, float>,
                         cudaFuncAttributeMaxDynamicSharedMemorySize, GEMM_SMEM);

    const int OFF1 = 0, OFF2 = 512, OFF3 = 1664, OFF4 = 2176;
    const int W1A_OFF = 0, W1B_OFF = 196608, W2A_OFF = 786432, W2B_OFF = 1048576;

    const long no4 = (long)O * 32, np4 = (long)T * 32;
    const long prep_total = (long)O + 4608 + WT_TOTAL + no4 + np4;

    zero_prep_k<<<(unsigned)((prep_total + 255) / 256), 256>>>(
        DEG, SUM, SQ, FLAG, W1a, W1b, W2a, W2b, WT,
        obj, pred, OBJH, PRH, O, no4, np4);
    probe_k<<<(T + 255) / 256, 256>>>(e32, FLAG, T);
    convert_k<<<(T + 255) / 256, 256>>>(e32, FLAG, ES, EO, DEG, T);

    // launch 3: GEMM1 (gathered)  <-- ncu capture slot
    mma_gemm_k<true, float><<<dim3(4, (T + 63) / 64), 256, GEMM_SMEM>>>(
        nullptr, OBJH, PRH, ES, EO, WT + W1A_OFF, b1a,
        A1, SUM + OFF1, SQ + OFF1, T, 512, 384);
    finalize_k<<<2, 256>>>(SUM + OFF1, SQ + OFF1, g1a, be1a, 1.f / T, 512, CA + OFF1, CB + OFF1);

    bnhalf_k<<<(unsigned)(((long)T * 128 + 255) / 256), 256>>>(
        A1, CA + OFF1, CB + OFF1, XH, (long)T * 128, 512);
    scan_k<<<1, 1024>>>(DEG, OFFS, CUR, O);
    fill_k<<<(T + 255) / 256, 256>>>(ES, EO, CUR, ELIST, T);

    mma_gemm_k<false, __half><<<dim3(9, (T + 63) / 64), 256, GEMM_SMEM>>>(
        XH, nullptr, nullptr, nullptr, nullptr, WT + W1B_OFF, b1b,
        A2, SUM + OFF2, SQ + OFF2, T, 1152, 512);
    finalize_k<<<5, 256>>>(SUM + OFF2, SQ + OFF2, g1b, be1b, 1.f / T, 1152, CA + OFF2, CB + OFF2);

    pool_k<<<O, 128>>>(A2, CA + OFF2, CB + OFF2, OFFS, ELIST, XH, O, (float)O);
    outp_k<<<(T * 32 + 255) / 256, 256>>>(A2, CA + OFF2, CB + OFF2, out_p, T);

    mma_gemm_k<false, float><<<dim3(4, (O + 63) / 64), 256, GEMM_SMEM>>>(
        XH, nullptr, nullptr, nullptr, nullptr, WT + W2A_OFF, b2a,
        A1, SUM + OFF3, SQ + OFF3, O, 512, 512);
    finalize_k<<<2, 256>>>(SUM + OFF3, SQ + OFF3, g2a, be2a, 1.f / O, 512, CA + OFF3, CB + OFF3);

    bnhalf_k<<<(unsigned)(((long)O * 128 + 255) / 256), 256>>>(
        A1, CA + OFF3, CB + OFF3, XH, (long)O * 128, 512);

    mma_gemm_k<false, float><<<dim3(1, (O + 63) / 64), 256, GEMM_SMEM>>>(
        XH, nullptr, nullptr, nullptr, nullptr, WT + W2B_OFF, b2b,
        A4, SUM + OFF4, SQ + OFF4, O, 128, 512);
    finalize_k<<<1, 256>>>(SUM + OFF4, SQ + OFF4, g2b, be2b, 1.f / O, 128, CA + OFF4, CB + OFF4);

    bn_out_k<<<(unsigned)(((long)O * 128 + 255) / 256), 256>>>(
        A4, CA + OFF4, CB + OFF4, out_obj, (long)O * 128, 128);
}